// round 1
// baseline (speedup 1.0000x reference)
#include <cuda_runtime.h>
#include <math.h>
#include <stdint.h>

// Problem constants
#define BB 4
#define NN 16384
#define DD 64
#define HH 8

// scratch (static __device__ globals: allocation-free per harness rules)
__device__ float g_cs [BB * NN * 64];            // per token: cos[0..31], sin[0..31]  (16.8 MB)
__device__ float g_kvp[BB * HH * 32 * 4096];     // per-(b,h,slab) partial kv          (16.8 MB)
__device__ float g_M  [BB * HH * 4096];          // folded (kv @ Wo_h)/N               (0.5 MB)

__device__ __forceinline__ float4 ld4(const float* p) { return *reinterpret_cast<const float4*>(p); }
__device__ __forceinline__ void   st4(float* p, float4 v) { *reinterpret_cast<float4*>(p) = v; }

// ---------------------------------------------------------------------------
// K0: cos/sin table.  f_j = pos * 64 * 10000^(-j/32), j = 0..31
// ---------------------------------------------------------------------------
__global__ void cs_kernel(const float* __restrict__ pos) {
    int idx = blockIdx.x * blockDim.x + threadIdx.x;
    if (idx >= BB * NN * 32) return;
    int j = idx & 31;
    int n = idx >> 5;
    float t = pos[n] * 64.0f;
    // inv_freq = exp(-j * ln(10000)/32)
    float inv = expf(-0.28782313662425572f * (float)j);
    float f = t * inv;
    g_cs[n * 64 + j]      = cosf(f);
    g_cs[n * 64 + 32 + j] = sinf(f);
}

// ---------------------------------------------------------------------------
// K1: per-(b,h,slab) fused  kproj+vproj -> LN -> RoPE(k) -> kv partial
// block: 256 threads, slab = 512 tokens = 8 chunks of 64
// thread (trow = tid>>4, ocol = tid&15): 4 tokens x (k-quad + v-quad)
// ---------------------------------------------------------------------------
#define KV_SMEM_FLOATS (8192 + 4352 + 4352 + 8448)
__global__ __launch_bounds__(256, 2)
void kv_kernel(const float* __restrict__ x, const float* __restrict__ Wk,
               const float* __restrict__ Wv) {
    extern __shared__ float sm[];
    float* sW  = sm;                    // [64][128] : cols 0..63 = Wk_h, 64..127 = Wv_h
    float* sXT = sm + 8192;             // [64][68]  : x transposed  (i, t)
    float* sCS = sXT + 64 * 68;         // [64][68]  : (t, 0..31 cos | 32..63 sin)
    float* sKV = sCS + 64 * 68;         // [64][132] : (t, 0..63 k_rot | 64..127 v_ln)

    const int s = blockIdx.x, h = blockIdx.y, b = blockIdx.z;
    const int tid  = threadIdx.x;
    const int trow = tid >> 4, ocol = tid & 15;
    const int t0  = trow << 2;
    const int oc4 = ocol << 2;
    const int jb  = (ocol & 7) << 2;                 // cos/sin quad base
    const float sgn = (ocol < 8) ? -1.0f : 1.0f;     // rotate_half sign

    // load per-head weight columns (once per block)
    for (int idx = tid; idx < 4096; idx += 256) {
        int i = idx >> 6, o = idx & 63;
        int g = i * 512 + h * 64 + o;
        sW[i * 128 + o]      = Wk[g];
        sW[i * 128 + 64 + o] = Wv[g];
    }

    float kv[4][4];
#pragma unroll
    for (int a = 0; a < 4; a++)
#pragma unroll
        for (int e = 0; e < 4; e++) kv[a][e] = 0.0f;

    for (int c = 0; c < 8; c++) {
        const size_t base = (size_t)b * NN + (size_t)s * 512 + (size_t)c * 64;

        // stage x (transposed) and cos/sin for this 64-token chunk
        for (int idx = tid; idx < 4096; idx += 256) {
            int t = idx >> 6, i = idx & 63;
            sXT[i * 68 + t] = x[(base + t) * 64 + i];
            sCS[t * 68 + i] = g_cs[(base + t) * 64 + i];
        }
        __syncthreads();

        // P1: projection GEMM  (4 tokens x 4 k-outs x 4 v-outs per thread)
        float ak[4][4], av[4][4];
#pragma unroll
        for (int a = 0; a < 4; a++)
#pragma unroll
            for (int e = 0; e < 4; e++) { ak[a][e] = 0.0f; av[a][e] = 0.0f; }

#pragma unroll 8
        for (int i = 0; i < 64; i++) {
            float4 xv = ld4(&sXT[i * 68 + t0]);
            float4 wk = ld4(&sW[i * 128 + oc4]);
            float4 wv = ld4(&sW[i * 128 + 64 + oc4]);
            float xs[4] = {xv.x, xv.y, xv.z, xv.w};
            float ks[4] = {wk.x, wk.y, wk.z, wk.w};
            float vs[4] = {wv.x, wv.y, wv.z, wv.w};
#pragma unroll
            for (int tt = 0; tt < 4; tt++)
#pragma unroll
                for (int j = 0; j < 4; j++) {
                    ak[tt][j] = fmaf(xs[tt], ks[j], ak[tt][j]);
                    av[tt][j] = fmaf(xs[tt], vs[j], av[tt][j]);
                }
        }

        // LN (k and v) + RoPE(k), all via shfl within the 16-lane token group
        const float inv64 = 1.0f / 64.0f;
#pragma unroll
        for (int tt = 0; tt < 4; tt++) {
            float sk = ak[tt][0] + ak[tt][1] + ak[tt][2] + ak[tt][3];
            float sk2 = ak[tt][0]*ak[tt][0] + ak[tt][1]*ak[tt][1] + ak[tt][2]*ak[tt][2] + ak[tt][3]*ak[tt][3];
            float sv = av[tt][0] + av[tt][1] + av[tt][2] + av[tt][3];
            float sv2 = av[tt][0]*av[tt][0] + av[tt][1]*av[tt][1] + av[tt][2]*av[tt][2] + av[tt][3]*av[tt][3];
#pragma unroll
            for (int m = 1; m <= 8; m <<= 1) {
                sk  += __shfl_xor_sync(0xffffffffu, sk,  m);
                sk2 += __shfl_xor_sync(0xffffffffu, sk2, m);
                sv  += __shfl_xor_sync(0xffffffffu, sv,  m);
                sv2 += __shfl_xor_sync(0xffffffffu, sv2, m);
            }
            float mk = sk * inv64;
            float vk = fmaxf(sk2 * inv64 - mk * mk, 0.0f);
            float rk = rsqrtf(vk + 1e-5f);
            float mv = sv * inv64;
            float vv = fmaxf(sv2 * inv64 - mv * mv, 0.0f);
            float rv = rsqrtf(vv + 1e-5f);

            float kn[4], vn[4];
#pragma unroll
            for (int j = 0; j < 4; j++) {
                kn[j] = (ak[tt][j] - mk) * rk;
                vn[j] = (av[tt][j] - mv) * rv;
            }
            float pk[4];
#pragma unroll
            for (int j = 0; j < 4; j++)
                pk[j] = __shfl_xor_sync(0xffffffffu, kn[j], 8);  // partner dim d^32

            int t = t0 + tt;
            float4 cq = ld4(&sCS[t * 68 + jb]);
            float4 sq = ld4(&sCS[t * 68 + 32 + jb]);
            float cs[4] = {cq.x, cq.y, cq.z, cq.w};
            float ss[4] = {sq.x, sq.y, sq.z, sq.w};
            float kr[4];
#pragma unroll
            for (int j = 0; j < 4; j++)
                kr[j] = kn[j] * cs[j] + sgn * pk[j] * ss[j];

            st4(&sKV[t * 132 + oc4],      make_float4(kr[0], kr[1], kr[2], kr[3]));
            st4(&sKV[t * 132 + 64 + oc4], make_float4(vn[0], vn[1], vn[2], vn[3]));
        }
        __syncthreads();

        // P2: kv[d][e] += sum_t k_rot[t][d] * v[t][e]   (d-quad = t0, e-quad = oc4)
#pragma unroll 4
        for (int t = 0; t < 64; t++) {
            float4 kq = ld4(&sKV[t * 132 + t0]);
            float4 vq = ld4(&sKV[t * 132 + 64 + oc4]);
            float kd[4] = {kq.x, kq.y, kq.z, kq.w};
            float ve[4] = {vq.x, vq.y, vq.z, vq.w};
#pragma unroll
            for (int a = 0; a < 4; a++)
#pragma unroll
                for (int e = 0; e < 4; e++)
                    kv[a][e] = fmaf(kd[a], ve[e], kv[a][e]);
        }
        // next-iteration staging is safe: next sKV write is gated by next __syncthreads()
    }

    // write deterministic per-slab partial
    float* dst = g_kvp + ((((size_t)b * HH + h) * 32 + s) << 12);
#pragma unroll
    for (int a = 0; a < 4; a++)
        st4(&dst[(t0 + a) * 64 + oc4], make_float4(kv[a][0], kv[a][1], kv[a][2], kv[a][3]));
}

// ---------------------------------------------------------------------------
// K2: reduce 32 slabs -> kv[b,h];  M[b,h] = kv @ Wo_h / N
// ---------------------------------------------------------------------------
__global__ void m_kernel(const float* __restrict__ Wo) {
    __shared__ float sKv[64 * 68];
    __shared__ float sWo[64 * 68];
    const int h = blockIdx.x, b = blockIdx.y;
    const int tid = threadIdx.x;

    const float* p0 = g_kvp + (((size_t)b * HH + h) * 32 << 12);
    for (int idx = tid; idx < 4096; idx += 256) {
        float acc = 0.0f;
#pragma unroll 8
        for (int s = 0; s < 32; s++) acc += p0[(size_t)s * 4096 + idx];
        int d = idx >> 6, e = idx & 63;
        sKv[d * 68 + e] = acc;
        sWo[d * 68 + e] = Wo[(h * 64 + d) * 64 + e];   // row d here is the e index of Wo_h
    }
    __syncthreads();

    const int d0 = (tid >> 4) << 2, o0 = (tid & 15) << 2;
    float m[4][4];
#pragma unroll
    for (int a = 0; a < 4; a++)
#pragma unroll
        for (int e = 0; e < 4; e++) m[a][e] = 0.0f;

#pragma unroll 4
    for (int e = 0; e < 64; e++) {
        float kd[4];
#pragma unroll
        for (int a = 0; a < 4; a++) kd[a] = sKv[(d0 + a) * 68 + e];
        float4 wq = ld4(&sWo[e * 68 + o0]);
        float wo[4] = {wq.x, wq.y, wq.z, wq.w};
#pragma unroll
        for (int a = 0; a < 4; a++)
#pragma unroll
            for (int j = 0; j < 4; j++) m[a][j] = fmaf(kd[a], wo[j], m[a][j]);
    }

    const float scale = 1.0f / (float)NN;
    float* dst = g_M + ((size_t)b * HH + h) * 4096;
#pragma unroll
    for (int a = 0; a < 4; a++)
        st4(&dst[(d0 + a) * 64 + o0],
            make_float4(m[a][0] * scale, m[a][1] * scale, m[a][2] * scale, m[a][3] * scale));
}

// ---------------------------------------------------------------------------
// K3: out[b,n] = sum_h RoPE(x Wq_h) @ M[b,h]
// block: (chunk of 64 tokens, b); loops 4 head-pairs
// ---------------------------------------------------------------------------
#define OUT_SMEM_FLOATS (8192 + 8704 + 4352 + 4352 + 8704)
__global__ __launch_bounds__(256, 1)
void out_kernel(const float* __restrict__ x, const float* __restrict__ Wq,
                float* __restrict__ out) {
    extern __shared__ float sm[];
    float* sWq = sm;                    // [64][128] : 2 heads of Wq
    float* sM  = sm + 8192;            // [128][68] : 2 heads of M (rows = hl*64+d)
    float* sXT = sM + 128 * 68;        // [64][68]
    float* sCS = sXT + 64 * 68;        // [64][68]
    float* sUT = sCS + 64 * 68;        // [128][68] : rotated q, transposed (r, t)

    const int chunk = blockIdx.x, b = blockIdx.y;
    const int tid  = threadIdx.x;
    const int trow = tid >> 4, ocol = tid & 15;
    const int t0  = trow << 2;
    const int oc4 = ocol << 2;
    const int jb  = (ocol & 7) << 2;
    const float sgn = (ocol < 8) ? -1.0f : 1.0f;
    const size_t base = (size_t)b * NN + (size_t)chunk * 64;

    for (int idx = tid; idx < 4096; idx += 256) {
        int t = idx >> 6, i = idx & 63;
        sXT[i * 68 + t] = x[(base + t) * 64 + i];
        sCS[t * 68 + i] = g_cs[(base + t) * 64 + i];
    }

    float oacc[4][4];
#pragma unroll
    for (int a = 0; a < 4; a++)
#pragma unroll
        for (int e = 0; e < 4; e++) oacc[a][e] = 0.0f;

    for (int hg = 0; hg < 4; hg++) {
        __syncthreads();   // previous iteration's readers of sWq/sM/sUT are done
        for (int idx = tid; idx < 4096; idx += 256) {
            int i = idx >> 6, o = idx & 63;
            sWq[i * 128 + o]      = Wq[i * 512 + (2 * hg) * 64 + o];
            sWq[i * 128 + 64 + o] = Wq[i * 512 + (2 * hg + 1) * 64 + o];
        }
        for (int idx = tid; idx < 8192; idx += 256) {
            int r = idx >> 6, o = idx & 63;
            int hh = 2 * hg + (r >> 6), d = r & 63;
            sM[r * 68 + o] = g_M[(((size_t)b * HH + hh) * 64 + d) * 64 + o];
        }
        __syncthreads();

        // q projection for 2 heads (quad per head per token)
        float ua[4][4], ub[4][4];
#pragma unroll
        for (int a = 0; a < 4; a++)
#pragma unroll
            for (int e = 0; e < 4; e++) { ua[a][e] = 0.0f; ub[a][e] = 0.0f; }

#pragma unroll 8
        for (int i = 0; i < 64; i++) {
            float4 xv = ld4(&sXT[i * 68 + t0]);
            float4 wa = ld4(&sWq[i * 128 + oc4]);
            float4 wb = ld4(&sWq[i * 128 + 64 + oc4]);
            float xs[4] = {xv.x, xv.y, xv.z, xv.w};
            float as[4] = {wa.x, wa.y, wa.z, wa.w};
            float bs[4] = {wb.x, wb.y, wb.z, wb.w};
#pragma unroll
            for (int tt = 0; tt < 4; tt++)
#pragma unroll
                for (int j = 0; j < 4; j++) {
                    ua[tt][j] = fmaf(xs[tt], as[j], ua[tt][j]);
                    ub[tt][j] = fmaf(xs[tt], bs[j], ub[tt][j]);
                }
        }

        // RoPE both heads (in registers), result kept as [tt][j]
#pragma unroll
        for (int tt = 0; tt < 4; tt++) {
            int t = t0 + tt;
            float4 cq = ld4(&sCS[t * 68 + jb]);
            float4 sq = ld4(&sCS[t * 68 + 32 + jb]);
            float cs[4] = {cq.x, cq.y, cq.z, cq.w};
            float ss[4] = {sq.x, sq.y, sq.z, sq.w};
            float pa[4], pb[4];
#pragma unroll
            for (int j = 0; j < 4; j++) {
                pa[j] = __shfl_xor_sync(0xffffffffu, ua[tt][j], 8);
                pb[j] = __shfl_xor_sync(0xffffffffu, ub[tt][j], 8);
            }
#pragma unroll
            for (int j = 0; j < 4; j++) {
                ua[tt][j] = ua[tt][j] * cs[j] + sgn * pa[j] * ss[j];
                ub[tt][j] = ub[tt][j] * cs[j] + sgn * pb[j] * ss[j];
            }
        }
        // write rotated q transposed: sUT[r][t]
#pragma unroll
        for (int j = 0; j < 4; j++) {
            st4(&sUT[(oc4 + j) * 68 + t0],       make_float4(ua[0][j], ua[1][j], ua[2][j], ua[3][j]));
            st4(&sUT[(64 + oc4 + j) * 68 + t0],  make_float4(ub[0][j], ub[1][j], ub[2][j], ub[3][j]));
        }
        __syncthreads();

        // out[t][o] += sum_r U[t][r] * M[r][o]
#pragma unroll 4
        for (int r = 0; r < 128; r++) {
            float4 uq = ld4(&sUT[r * 68 + t0]);
            float4 mq = ld4(&sM[r * 68 + oc4]);
            float ut[4] = {uq.x, uq.y, uq.z, uq.w};
            float mo[4] = {mq.x, mq.y, mq.z, mq.w};
#pragma unroll
            for (int tt = 0; tt < 4; tt++)
#pragma unroll
                for (int j = 0; j < 4; j++)
                    oacc[tt][j] = fmaf(ut[tt], mo[j], oacc[tt][j]);
        }
    }

#pragma unroll
    for (int tt = 0; tt < 4; tt++)
        st4(&out[(base + t0 + tt) * 64 + oc4],
            make_float4(oacc[tt][0], oacc[tt][1], oacc[tt][2], oacc[tt][3]));
}

// ---------------------------------------------------------------------------
extern "C" void kernel_launch(void* const* d_in, const int* in_sizes, int n_in,
                              void* d_out, int out_size) {
    const float* x   = (const float*)d_in[0];
    const float* pos = (const float*)d_in[1];
    const float* Wq  = (const float*)d_in[2];
    const float* Wk  = (const float*)d_in[3];
    const float* Wv  = (const float*)d_in[4];
    const float* Wo  = (const float*)d_in[5];
    float* out = (float*)d_out;

    cudaFuncSetAttribute(kv_kernel,  cudaFuncAttributeMaxDynamicSharedMemorySize,
                         KV_SMEM_FLOATS * (int)sizeof(float));
    cudaFuncSetAttribute(out_kernel, cudaFuncAttributeMaxDynamicSharedMemorySize,
                         OUT_SMEM_FLOATS * (int)sizeof(float));

    cs_kernel<<<(BB * NN * 32 + 255) / 256, 256>>>(pos);
    kv_kernel<<<dim3(32, HH, BB), 256, KV_SMEM_FLOATS * sizeof(float)>>>(x, Wk, Wv);
    m_kernel<<<dim3(HH, BB), 256>>>(Wo);
    out_kernel<<<dim3(NN / 64, BB), 256, OUT_SMEM_FLOATS * sizeof(float)>>>(x, Wq, out);
}

// round 3
// speedup vs baseline: 1.7451x; 1.7451x over previous
#include <cuda_runtime.h>
#include <math.h>
#include <stdint.h>

// Problem constants
#define BB 4
#define NN 16384
#define DD 64
#define HH 8

// scratch (static __device__ globals: allocation-free per harness rules)
__device__ float g_cs [BB * NN * 64];            // per token: cos[0..31], sin[0..31]
__device__ float g_kvp[BB * HH * 32 * 4096];     // per-(b,h,slab) partial kv
__device__ float g_M  [BB * HH * 4096];          // folded (kv @ Wo_h)/N

__device__ __forceinline__ float4 ld4(const float* p) { return *reinterpret_cast<const float4*>(p); }
__device__ __forceinline__ void   st4(float* p, float4 v) { *reinterpret_cast<float4*>(p) = v; }

// ---------------------------------------------------------------------------
// K0: cos/sin table.  f_j = pos * 64 * 10000^(-j/32), j = 0..31
// ---------------------------------------------------------------------------
__global__ void cs_kernel(const float* __restrict__ pos) {
    int idx = blockIdx.x * blockDim.x + threadIdx.x;
    if (idx >= BB * NN * 32) return;
    int j = idx & 31;
    int n = idx >> 5;
    float t = pos[n] * 64.0f;
    float inv = expf(-0.28782313662425572f * (float)j);  // 10000^(-j/32)
    float f = t * inv;
    g_cs[n * 64 + j]      = cosf(f);
    g_cs[n * 64 + 32 + j] = sinf(f);
}

// ---------------------------------------------------------------------------
// K1: per-(b,h,slab) fused  kproj+vproj -> LN -> RoPE(k) -> kv partial
// block: 256 threads, slab = 512 tokens = 8 chunks of 64
// smem: sW [64][128]; union region: {sXT[64][68] + sCS[64][68]} alias {sKV[64][132]}
// ---------------------------------------------------------------------------
#define KV_SMEM_FLOATS (8192 + 8704)
__global__ __launch_bounds__(256, 3)
void kv_kernel(const float* __restrict__ x, const float* __restrict__ Wk,
               const float* __restrict__ Wv) {
    extern __shared__ float sm[];
    float* sW  = sm;                    // [64][128] : cols 0..63 = Wk_h, 64..127 = Wv_h
    float* sU  = sm + 8192;             // union region (8704 floats)
    float* sXT = sU;                    // [64][68]  : x transposed (i, t)
    float* sCS = sU + 4352;             // [64][68]  : (t, cos|sin)
    float* sKV = sU;                    // [64][132] : ALIASED, live only in P2

    const int s = blockIdx.x, h = blockIdx.y, b = blockIdx.z;
    const int tid  = threadIdx.x;
    const int trow = tid >> 4, ocol = tid & 15;
    const int t0  = trow << 2;
    const int oc4 = ocol << 2;
    const int jb  = (ocol & 7) << 2;
    const float sgn = (ocol < 8) ? -1.0f : 1.0f;

    for (int idx = tid; idx < 4096; idx += 256) {
        int i = idx >> 6, o = idx & 63;
        int g = i * 512 + h * 64 + o;
        sW[i * 128 + o]      = Wk[g];
        sW[i * 128 + 64 + o] = Wv[g];
    }

    float kv[4][4];
#pragma unroll
    for (int a = 0; a < 4; a++)
#pragma unroll
        for (int e = 0; e < 4; e++) kv[a][e] = 0.0f;

    for (int c = 0; c < 8; c++) {
        const size_t base = (size_t)b * NN + (size_t)s * 512 + (size_t)c * 64;

        // stage x (transposed) and cos/sin for this 64-token chunk
        for (int idx = tid; idx < 4096; idx += 256) {
            int t = idx >> 6, i = idx & 63;
            sXT[i * 68 + t] = x[(base + t) * 64 + i];
            sCS[t * 68 + i] = g_cs[(base + t) * 64 + i];
        }
        __syncthreads();

        // P1: projection GEMM (4 tokens x 4 k-outs x 4 v-outs per thread)
        float ak[4][4], av[4][4];
#pragma unroll
        for (int a = 0; a < 4; a++)
#pragma unroll
            for (int e = 0; e < 4; e++) { ak[a][e] = 0.0f; av[a][e] = 0.0f; }

#pragma unroll 8
        for (int i = 0; i < 64; i++) {
            float4 xv = ld4(&sXT[i * 68 + t0]);
            float4 wk = ld4(&sW[i * 128 + oc4]);
            float4 wv = ld4(&sW[i * 128 + 64 + oc4]);
            float xs[4] = {xv.x, xv.y, xv.z, xv.w};
            float ks[4] = {wk.x, wk.y, wk.z, wk.w};
            float vs[4] = {wv.x, wv.y, wv.z, wv.w};
#pragma unroll
            for (int tt = 0; tt < 4; tt++)
#pragma unroll
                for (int j = 0; j < 4; j++) {
                    ak[tt][j] = fmaf(xs[tt], ks[j], ak[tt][j]);
                    av[tt][j] = fmaf(xs[tt], vs[j], av[tt][j]);
                }
        }

        // LN(k,v) + RoPE(k); results kept in registers: ak := k_rot, av := v_ln
        const float inv64 = 1.0f / 64.0f;
#pragma unroll
        for (int tt = 0; tt < 4; tt++) {
            float sk = ak[tt][0] + ak[tt][1] + ak[tt][2] + ak[tt][3];
            float sk2 = ak[tt][0]*ak[tt][0] + ak[tt][1]*ak[tt][1] + ak[tt][2]*ak[tt][2] + ak[tt][3]*ak[tt][3];
            float sv = av[tt][0] + av[tt][1] + av[tt][2] + av[tt][3];
            float sv2 = av[tt][0]*av[tt][0] + av[tt][1]*av[tt][1] + av[tt][2]*av[tt][2] + av[tt][3]*av[tt][3];
#pragma unroll
            for (int m = 1; m <= 8; m <<= 1) {
                sk  += __shfl_xor_sync(0xffffffffu, sk,  m);
                sk2 += __shfl_xor_sync(0xffffffffu, sk2, m);
                sv  += __shfl_xor_sync(0xffffffffu, sv,  m);
                sv2 += __shfl_xor_sync(0xffffffffu, sv2, m);
            }
            float mk = sk * inv64;
            float vk = fmaxf(sk2 * inv64 - mk * mk, 0.0f);
            float rk = rsqrtf(vk + 1e-5f);
            float mv = sv * inv64;
            float vv = fmaxf(sv2 * inv64 - mv * mv, 0.0f);
            float rv = rsqrtf(vv + 1e-5f);

            float kn[4];
#pragma unroll
            for (int j = 0; j < 4; j++) {
                kn[j]     = (ak[tt][j] - mk) * rk;
                av[tt][j] = (av[tt][j] - mv) * rv;
            }
            float pk[4];
#pragma unroll
            for (int j = 0; j < 4; j++)
                pk[j] = __shfl_xor_sync(0xffffffffu, kn[j], 8);  // partner dim d^32

            int t = t0 + tt;
            float4 cq = ld4(&sCS[t * 68 + jb]);
            float4 sq = ld4(&sCS[t * 68 + 32 + jb]);
            float cs[4] = {cq.x, cq.y, cq.z, cq.w};
            float ss[4] = {sq.x, sq.y, sq.z, sq.w};
#pragma unroll
            for (int j = 0; j < 4; j++)
                ak[tt][j] = kn[j] * cs[j] + sgn * pk[j] * ss[j];
        }
        __syncthreads();   // all sXT/sCS reads done before aliased sKV writes

#pragma unroll
        for (int tt = 0; tt < 4; tt++) {
            int t = t0 + tt;
            st4(&sKV[t * 132 + oc4],      make_float4(ak[tt][0], ak[tt][1], ak[tt][2], ak[tt][3]));
            st4(&sKV[t * 132 + 64 + oc4], make_float4(av[tt][0], av[tt][1], av[tt][2], av[tt][3]));
        }
        __syncthreads();

        // P2: kv[d][e] += sum_t k_rot[t][d] * v[t][e]
#pragma unroll 4
        for (int t = 0; t < 64; t++) {
            float4 kq = ld4(&sKV[t * 132 + t0]);
            float4 vq = ld4(&sKV[t * 132 + 64 + oc4]);
            float kd[4] = {kq.x, kq.y, kq.z, kq.w};
            float ve[4] = {vq.x, vq.y, vq.z, vq.w};
#pragma unroll
            for (int a = 0; a < 4; a++)
#pragma unroll
                for (int e = 0; e < 4; e++)
                    kv[a][e] = fmaf(kd[a], ve[e], kv[a][e]);
        }
        __syncthreads();   // P2 reads done before next chunk's aliased staging
    }

    float* dst = g_kvp + ((((size_t)b * HH + h) * 32 + s) << 12);
#pragma unroll
    for (int a = 0; a < 4; a++)
        st4(&dst[(t0 + a) * 64 + oc4], make_float4(kv[a][0], kv[a][1], kv[a][2], kv[a][3]));
}

// ---------------------------------------------------------------------------
// K2: reduce 32 slabs -> kv[b,h];  M[b,h] = kv @ Wo_h / N
// ---------------------------------------------------------------------------
__global__ void m_kernel(const float* __restrict__ Wo) {
    __shared__ float sKv[64 * 68];
    __shared__ float sWo[64 * 68];
    const int h = blockIdx.x, b = blockIdx.y;
    const int tid = threadIdx.x;

    const float* p0 = g_kvp + (((size_t)b * HH + h) * 32 << 12);
    for (int idx = tid; idx < 4096; idx += 256) {
        float acc = 0.0f;
#pragma unroll 8
        for (int s = 0; s < 32; s++) acc += p0[(size_t)s * 4096 + idx];
        int d = idx >> 6, e = idx & 63;
        sKv[d * 68 + e] = acc;
        sWo[d * 68 + e] = Wo[(h * 64 + d) * 64 + e];
    }
    __syncthreads();

    const int d0 = (tid >> 4) << 2, o0 = (tid & 15) << 2;
    float m[4][4];
#pragma unroll
    for (int a = 0; a < 4; a++)
#pragma unroll
        for (int e = 0; e < 4; e++) m[a][e] = 0.0f;

#pragma unroll 4
    for (int e = 0; e < 64; e++) {
        float kd[4];
#pragma unroll
        for (int a = 0; a < 4; a++) kd[a] = sKv[(d0 + a) * 68 + e];
        float4 wq = ld4(&sWo[e * 68 + o0]);
        float wo[4] = {wq.x, wq.y, wq.z, wq.w};
#pragma unroll
        for (int a = 0; a < 4; a++)
#pragma unroll
            for (int j = 0; j < 4; j++) m[a][j] = fmaf(kd[a], wo[j], m[a][j]);
    }

    const float scale = 1.0f / (float)NN;
    float* dst = g_M + ((size_t)b * HH + h) * 4096;
#pragma unroll
    for (int a = 0; a < 4; a++)
        st4(&dst[(d0 + a) * 64 + o0],
            make_float4(m[a][0] * scale, m[a][1] * scale, m[a][2] * scale, m[a][3] * scale));
}

// ---------------------------------------------------------------------------
// K3: out[b,n] = sum_h RoPE(x Wq_h) @ M[b,h]
// block = 64 tokens, loop over 8 heads; sUT aliased over sWq
// smem: sU(union Wq/UT)[64][68] + sM[64][68] + sXT[64][68] + sCS[64][68]
// ---------------------------------------------------------------------------
#define OUT_SMEM_FLOATS (4352 * 4)
__global__ __launch_bounds__(256, 3)
void out_kernel(const float* __restrict__ x, const float* __restrict__ Wq,
                float* __restrict__ out) {
    extern __shared__ float sm[];
    float* sU  = sm;                    // [64][68] union: Wq_h (i,o) then U^T (r,t)
    float* sM  = sm + 4352;             // [64][68] : M_h (d, o)
    float* sXT = sm + 8704;             // [64][68]
    float* sCS = sm + 13056;            // [64][68]

    const int chunk = blockIdx.x, b = blockIdx.y;
    const int tid  = threadIdx.x;
    const int trow = tid >> 4, ocol = tid & 15;
    const int t0  = trow << 2;
    const int oc4 = ocol << 2;
    const int jb  = (ocol & 7) << 2;
    const float sgn = (ocol < 8) ? -1.0f : 1.0f;
    const size_t base = (size_t)b * NN + (size_t)chunk * 64;

    for (int idx = tid; idx < 4096; idx += 256) {
        int t = idx >> 6, i = idx & 63;
        sXT[i * 68 + t] = x[(base + t) * 64 + i];
        sCS[t * 68 + i] = g_cs[(base + t) * 64 + i];
    }

    float oacc[4][4];
#pragma unroll
    for (int a = 0; a < 4; a++)
#pragma unroll
        for (int e = 0; e < 4; e++) oacc[a][e] = 0.0f;

    for (int h = 0; h < HH; h++) {
        __syncthreads();   // prior iter's sU/sM readers done before overwrite
        for (int idx = tid; idx < 4096; idx += 256) {
            int i = idx >> 6, o = idx & 63;
            sU[i * 68 + o] = Wq[i * 512 + h * 64 + o];
            sM[i * 68 + o] = g_M[(((size_t)b * HH + h) * 64 + i) * 64 + o];
        }
        __syncthreads();

        // q projection for this head
        float ua[4][4];
#pragma unroll
        for (int a = 0; a < 4; a++)
#pragma unroll
            for (int e = 0; e < 4; e++) ua[a][e] = 0.0f;

#pragma unroll 8
        for (int i = 0; i < 64; i++) {
            float4 xv = ld4(&sXT[i * 68 + t0]);
            float4 wa = ld4(&sU[i * 68 + oc4]);
            float xs[4] = {xv.x, xv.y, xv.z, xv.w};
            float as[4] = {wa.x, wa.y, wa.z, wa.w};
#pragma unroll
            for (int tt = 0; tt < 4; tt++)
#pragma unroll
                for (int j = 0; j < 4; j++)
                    ua[tt][j] = fmaf(xs[tt], as[j], ua[tt][j]);
        }

        // RoPE (in registers)
#pragma unroll
        for (int tt = 0; tt < 4; tt++) {
            int t = t0 + tt;
            float4 cq = ld4(&sCS[t * 68 + jb]);
            float4 sq = ld4(&sCS[t * 68 + 32 + jb]);
            float cs[4] = {cq.x, cq.y, cq.z, cq.w};
            float ss[4] = {sq.x, sq.y, sq.z, sq.w};
            float pa[4];
#pragma unroll
            for (int j = 0; j < 4; j++)
                pa[j] = __shfl_xor_sync(0xffffffffu, ua[tt][j], 8);
#pragma unroll
            for (int j = 0; j < 4; j++)
                ua[tt][j] = ua[tt][j] * cs[j] + sgn * pa[j] * ss[j];
        }
        __syncthreads();   // all sU(Wq) reads done before aliased U^T writes

#pragma unroll
        for (int j = 0; j < 4; j++)
            st4(&sU[(oc4 + j) * 68 + t0], make_float4(ua[0][j], ua[1][j], ua[2][j], ua[3][j]));
        __syncthreads();

        // out[t][o] += sum_r U[t][r] * M[r][o]
#pragma unroll 4
        for (int r = 0; r < 64; r++) {
            float4 uq = ld4(&sU[r * 68 + t0]);
            float4 mq = ld4(&sM[r * 68 + oc4]);
            float ut[4] = {uq.x, uq.y, uq.z, uq.w};
            float mo[4] = {mq.x, mq.y, mq.z, mq.w};
#pragma unroll
            for (int tt = 0; tt < 4; tt++)
#pragma unroll
                for (int j = 0; j < 4; j++)
                    oacc[tt][j] = fmaf(ut[tt], mo[j], oacc[tt][j]);
        }
    }

#pragma unroll
    for (int tt = 0; tt < 4; tt++)
        st4(&out[(base + t0 + tt) * 64 + oc4],
            make_float4(oacc[tt][0], oacc[tt][1], oacc[tt][2], oacc[tt][3]));
}

// ---------------------------------------------------------------------------
extern "C" void kernel_launch(void* const* d_in, const int* in_sizes, int n_in,
                              void* d_out, int out_size) {
    const float* x   = (const float*)d_in[0];
    const float* pos = (const float*)d_in[1];
    const float* Wq  = (const float*)d_in[2];
    const float* Wk  = (const float*)d_in[3];
    const float* Wv  = (const float*)d_in[4];
    const float* Wo  = (const float*)d_in[5];
    float* out = (float*)d_out;

    cudaFuncSetAttribute(kv_kernel,  cudaFuncAttributeMaxDynamicSharedMemorySize,
                         KV_SMEM_FLOATS * (int)sizeof(float));
    cudaFuncSetAttribute(out_kernel, cudaFuncAttributeMaxDynamicSharedMemorySize,
                         OUT_SMEM_FLOATS * (int)sizeof(float));

    cs_kernel<<<(BB * NN * 32 + 255) / 256, 256>>>(pos);
    kv_kernel<<<dim3(32, HH, BB), 256, KV_SMEM_FLOATS * sizeof(float)>>>(x, Wk, Wv);
    m_kernel<<<dim3(HH, BB), 256>>>(Wo);
    out_kernel<<<dim3(NN / 64, BB), 256, OUT_SMEM_FLOATS * sizeof(float)>>>(x, Wq, out);
}